// round 1
// baseline (speedup 1.0000x reference)
#include <cuda_runtime.h>
#include <cuda_bf16.h>

// Problem shape (fixed for this dataset entry)
#define NN 8
#define LL 8192
#define SS 8192
#define HH 8
#define DD 32
#define ROWSTRIDE (HH*DD)      // 256 floats per token row (all heads)
#define CHUNKS 8
#define TOK_PER_CHUNK (SS/CHUNKS)   // 1024
#define L_PER_CHUNK (LL/CHUNKS)     // 1024
#define NH (NN*HH)                  // 64
#define PART_STRIDE 1056            // 1024 KV + 32 Ksum

// Deterministic scratch: per-(chunk, n*h) partial KV (32x32) + Ksum (32)
__device__ __align__(16) float g_part[CHUNKS * NH * PART_STRIDE];

__device__ __forceinline__ float elu1(float x) {
    return x > 0.0f ? x + 1.0f : __expf(x);
}

// ---------------------------------------------------------------------------
// Phase 1: partial KV state per (n,h,chunk).
// Block = 256 threads. Each thread owns KV[d][v0..v0+3], d = tid>>3, v0=(tid&7)*4.
// Tokens streamed through shared in tiles of 16 (float4 global loads).
// ---------------------------------------------------------------------------
__global__ void __launch_bounds__(256, 4)
phase1_kernel(const float* __restrict__ K, const float* __restrict__ V)
{
    const int nh    = blockIdx.x;          // 0..63
    const int chunk = blockIdx.y;          // 0..7
    const int n = nh >> 3, h = nh & 7;
    const int s0 = chunk * TOK_PER_CHUNK;

    __shared__ __align__(16) float sK[16][32];
    __shared__ __align__(16) float sV[16][32];

    const int tid = threadIdx.x;
    const int d  = tid >> 3;
    const int v0 = (tid & 7) * 4;

    // loader mapping: 256 float4 = 16 tokens * (8 K-quads + 8 V-quads)
    const int lt   = tid >> 4;             // token within tile, 0..15
    const int lq   = tid & 15;             // quad id
    const bool isK = (lq < 8);
    const int lcol = (lq & 7) * 4;

    const size_t headoff = (size_t)n * SS * ROWSTRIDE + (size_t)h * DD;
    const float* src_base = (isK ? K : V) + headoff + (size_t)lcol;

    float a0 = 0.f, a1 = 0.f, a2 = 0.f, a3 = 0.f, ksum = 0.f;

    for (int s = s0; s < s0 + TOK_PER_CHUNK; s += 16) {
        float4 val = *(const float4*)(src_base + (size_t)(s + lt) * ROWSTRIDE);
        if (isK) {
            val.x = elu1(val.x); val.y = elu1(val.y);
            val.z = elu1(val.z); val.w = elu1(val.w);
            *(float4*)&sK[lt][lcol] = val;
        } else {
            *(float4*)&sV[lt][lcol] = val;
        }
        __syncthreads();
        #pragma unroll
        for (int tt = 0; tt < 16; tt++) {
            float  kd = sK[tt][d];
            float4 vv = *(const float4*)&sV[tt][v0];
            a0 = fmaf(kd, vv.x, a0);
            a1 = fmaf(kd, vv.y, a1);
            a2 = fmaf(kd, vv.z, a2);
            a3 = fmaf(kd, vv.w, a3);
            ksum += kd;                    // uniform across the 8 v-threads of d
        }
        __syncthreads();
    }

    float* part = g_part + ((size_t)chunk * NH + nh) * PART_STRIDE;
    *(float4*)&part[d * 32 + v0] = make_float4(a0, a1, a2, a3);
    if ((tid & 7) == 0) part[1024 + d] = ksum;
}

// ---------------------------------------------------------------------------
// Phase 2: out = phi(Q) @ KV / (phi(Q) . Ksum + eps)
// Block = 256 threads (8 warps). Block reduces the 8 partials into shared,
// each lane holds KV column `lane` in 32 registers. One warp per Q row:
// stage phi(Q) row in shared, 8 broadcast LDS.128 + 32 FMA, butterfly for Z.
// ---------------------------------------------------------------------------
__global__ void __launch_bounds__(256, 4)
phase2_kernel(const float* __restrict__ Q, float* __restrict__ out)
{
    const int nh    = blockIdx.x;
    const int chunk = blockIdx.y;
    const int n = nh >> 3, h = nh & 7;
    const int l0 = chunk * L_PER_CHUNK;

    __shared__ __align__(16) float sKV[1024];
    __shared__ float sKs[32];
    __shared__ __align__(16) float qbuf[8][32];

    const int tid = threadIdx.x;

    // reduce 8 chunk-partials
    for (int i = tid; i < PART_STRIDE; i += 256) {
        float s = 0.f;
        #pragma unroll
        for (int c = 0; c < CHUNKS; c++)
            s += g_part[((size_t)c * NH + nh) * PART_STRIDE + i];
        if (i < 1024) sKV[i] = s; else sKs[i - 1024] = s;
    }
    __syncthreads();

    const int w    = tid >> 5;
    const int lane = tid & 31;

    float kv[32];
    #pragma unroll
    for (int dd2 = 0; dd2 < 32; dd2++) kv[dd2] = sKV[dd2 * 32 + lane];
    const float ks = sKs[lane];

    const size_t base = (size_t)n * LL * ROWSTRIDE + (size_t)h * DD + lane;
    const float* qb = Q + base;
    float*       ob = out + base;

    for (int l = l0 + w; l < l0 + L_PER_CHUNK; l += 8) {
        const size_t off = (size_t)l * ROWSTRIDE;
        float x  = qb[off];
        float qf = elu1(x);
        qbuf[w][lane] = qf;
        __syncwarp();

        float acc = 0.f;
        const float4* q4 = (const float4*)qbuf[w];
        #pragma unroll
        for (int j = 0; j < 8; j++) {
            float4 qv = q4[j];
            acc = fmaf(qv.x, kv[4*j + 0], acc);
            acc = fmaf(qv.y, kv[4*j + 1], acc);
            acc = fmaf(qv.z, kv[4*j + 2], acc);
            acc = fmaf(qv.w, kv[4*j + 3], acc);
        }

        // Z = 1 / (phi(q) . Ksum + eps), butterfly reduce
        float t = qf * ks;
        t += __shfl_xor_sync(0xFFFFFFFFu, t, 16);
        t += __shfl_xor_sync(0xFFFFFFFFu, t, 8);
        t += __shfl_xor_sync(0xFFFFFFFFu, t, 4);
        t += __shfl_xor_sync(0xFFFFFFFFu, t, 2);
        t += __shfl_xor_sync(0xFFFFFFFFu, t, 1);
        float z = 1.0f / (t + 1e-6f);

        ob[off] = acc * z;
        __syncwarp();   // protect qbuf before next overwrite
    }
}

extern "C" void kernel_launch(void* const* d_in, const int* in_sizes, int n_in,
                              void* d_out, int out_size)
{
    const float* queries = (const float*)d_in[0];
    const float* keys    = (const float*)d_in[1];
    const float* values  = (const float*)d_in[2];
    float* out = (float*)d_out;

    dim3 grid1(NH, CHUNKS);
    phase1_kernel<<<grid1, 256>>>(keys, values);

    dim3 grid2(NH, CHUNKS);
    phase2_kernel<<<grid2, 256>>>(queries, out);
}

// round 2
// speedup vs baseline: 1.3562x; 1.3562x over previous
#include <cuda_runtime.h>
#include <cuda_bf16.h>

// Shape fixed for this dataset entry
#define NN 8
#define LL 8192
#define SS 8192
#define HH 8
#define RS 256              // floats per token row (H*D)
#define NH 64               // N*H

#define P1C 16              // phase1 S-chunks
#define P1TOK 512           // tokens per phase1 block
#define TILE 32             // K staging tile (tokens)
#define NTILES (P1TOK/TILE) // 16
#define KROW 36             // padded K tile row stride (floats)
#define PART 1056           // partial: 1024 KV ([v][d]) + 32 Ksum

#define P2C 8               // phase2 L-chunks

// Deterministic scratch (per-chunk partial states)
__device__ __align__(16) float g_part[P1C * NH * PART];

typedef unsigned long long u64;

__device__ __forceinline__ u64 fma2(u64 a, u64 b, u64 c) {
    u64 d;
    asm("fma.rn.f32x2 %0, %1, %2, %3;" : "=l"(d) : "l"(a), "l"(b), "l"(c));
    return d;
}
__device__ __forceinline__ u64 dup2(float v) {
    u64 d;
    asm("mov.b64 %0, {%1, %1};" : "=l"(d) : "f"(v));
    return d;
}
__device__ __forceinline__ float2 unp(u64 a) {
    float2 r;
    asm("mov.b64 {%0, %1}, %2;" : "=f"(r.x), "=f"(r.y) : "l"(a));
    return r;
}
__device__ __forceinline__ float elu1(float x) {
    return x > 0.0f ? x + 1.0f : __expf(x);   // elu(x)+1 = exp(x) for x<=0
}

// ---------------------------------------------------------------------------
// Phase 1: per-(nh, chunk) partial KV (32x32) + Ksum (32).
// 8 warps/block, each warp owns a full 32x32 accumulator (32 regs/lane,
// lane = v column, d packed in f32x2 pairs) over a disjoint token subset.
// elu(K) staged double-buffered in shared; V read straight from global.
// ---------------------------------------------------------------------------
__global__ void __launch_bounds__(256)
phase1_kernel(const float* __restrict__ K, const float* __restrict__ V)
{
    __shared__ __align__(16) float sK[2][TILE * KROW];   // elu'd K tiles
    __shared__ __align__(16) float sred[8 * 1088];       // epilogue reduce

    const int tid  = threadIdx.x;
    const int w    = tid >> 5, lane = tid & 31;
    const int nh   = blockIdx.x, chunk = blockIdx.y;
    const int n = nh >> 3, h = nh & 7;
    const int s0 = chunk * P1TOK;

    // staging map: thread -> (token stok, quad sq), 1 float4 per tile
    const int stok = tid >> 3, sq = tid & 7;
    const float* Ksrc = K + ((size_t)n * SS + s0 + stok) * RS + h * 32 + sq * 4;
    const float* Vb   = V + ((size_t)n * SS + s0) * RS + h * 32 + lane;

    u64 acc[16];
    #pragma unroll
    for (int j = 0; j < 16; j++) acc[j] = 0ULL;
    float4 ksum4 = make_float4(0.f, 0.f, 0.f, 0.f);

    // stage tile 0
    {
        float4 kq = *(const float4*)Ksrc;
        kq.x = elu1(kq.x); kq.y = elu1(kq.y); kq.z = elu1(kq.z); kq.w = elu1(kq.w);
        ksum4.x += kq.x; ksum4.y += kq.y; ksum4.z += kq.z; ksum4.w += kq.w;
        *(float4*)&sK[0][stok * KROW + sq * 4] = kq;
    }
    __syncthreads();

    for (int tile = 0; tile < NTILES; ++tile) {
        float4 kn;
        const bool has = (tile + 1) < NTILES;
        if (has) kn = *(const float4*)(Ksrc + (size_t)(tile + 1) * TILE * RS);

        // process current tile: warp w owns tokens w*4 .. w*4+3 (disjoint)
        const float* kb = &sK[tile & 1][0];
        float vv[4];
        #pragma unroll
        for (int t = 0; t < 4; t++)
            vv[t] = Vb[(size_t)(tile * TILE + w * 4 + t) * RS];
        #pragma unroll
        for (int t = 0; t < 4; t++) {
            u64 v2 = dup2(vv[t]);
            const u64* kp = (const u64*)(kb + (w * 4 + t) * KROW);  // broadcast LDS
            #pragma unroll
            for (int j = 0; j < 16; j++) acc[j] = fma2(kp[j], v2, acc[j]);
        }

        if (has) {
            kn.x = elu1(kn.x); kn.y = elu1(kn.y); kn.z = elu1(kn.z); kn.w = elu1(kn.w);
            ksum4.x += kn.x; ksum4.y += kn.y; ksum4.z += kn.z; ksum4.w += kn.w;
            *(float4*)&sK[(tile + 1) & 1][stok * KROW + sq * 4] = kn;
        }
        __syncthreads();
    }

    // ---- epilogue: reduce 8 warp partials, write [v][d] + ksum ----
    float* swr = &sred[w * 1088];
    #pragma unroll
    for (int j = 0; j < 16; j++)
        *(u64*)&swr[lane * 34 + 2 * j] = acc[j];   // row = v(lane), col = d
    __syncthreads();

    float* gp = g_part + ((size_t)chunk * NH + nh) * PART;
    #pragma unroll
    for (int f = tid; f < 1024; f += 256) {
        int v = f >> 5, d = f & 31;
        float s = 0.f;
        #pragma unroll
        for (int w2 = 0; w2 < 8; w2++) s += sred[w2 * 1088 + v * 34 + d];
        gp[f] = s;
    }
    __syncthreads();
    *(float4*)&sred[(tid >> 3) * 36 + (tid & 7) * 4] = ksum4;   // reuse sred
    __syncthreads();
    if (tid < 32) {
        float s = 0.f;
        #pragma unroll
        for (int g = 0; g < 32; g++) s += sred[g * 36 + tid];
        gp[1024 + tid] = s;
    }
}

// ---------------------------------------------------------------------------
// Phase 2: out = phi(Q) @ KV / (phi(Q).Ksum + eps)
// Block reduces the 16 partials; each lane keeps KV column `lane` as 16
// packed d-pairs. 4 rows in flight per warp iteration (ILP for LDG + SHFL).
// ---------------------------------------------------------------------------
__global__ void __launch_bounds__(256)
phase2_kernel(const float* __restrict__ Q, float* __restrict__ out)
{
    __shared__ __align__(16) float sKV[32 * 34];        // [v*34 + d]
    __shared__ float sKs[32];
    __shared__ __align__(16) float qbuf[8][4][32];

    const int tid  = threadIdx.x;
    const int w    = tid >> 5, lane = tid & 31;
    const int nh   = blockIdx.x, chunk = blockIdx.y;
    const int n = nh >> 3, h = nh & 7;

    // reduce the 16 chunk-partials
    for (int f = tid; f < PART; f += 256) {
        float s = 0.f;
        #pragma unroll
        for (int c = 0; c < P1C; c++)
            s += g_part[((size_t)c * NH + nh) * PART + f];
        if (f < 1024) sKV[(f >> 5) * 34 + (f & 31)] = s;
        else          sKs[f - 1024] = s;
    }
    __syncthreads();

    u64 kv[16];
    const u64* kp = (const u64*)&sKV[lane * 34];
    #pragma unroll
    for (int j = 0; j < 16; j++) kv[j] = kp[j];
    const float ks = sKs[lane];

    const size_t base = (size_t)n * LL * RS + h * 32 + lane;
    const int r0 = chunk * 1024 + w * 128;

    for (int r = r0; r < r0 + 128; r += 4) {
        float qf[4];
        #pragma unroll
        for (int i = 0; i < 4; i++) {
            float x = Q[base + (size_t)(r + i) * RS];
            qf[i] = elu1(x);
            qbuf[w][i][lane] = qf[i];
        }
        __syncwarp();

        u64 a0 = 0, a1 = 0, a2 = 0, a3 = 0;
        const u64* q0 = (const u64*)qbuf[w][0];
        const u64* q1 = (const u64*)qbuf[w][1];
        const u64* q2 = (const u64*)qbuf[w][2];
        const u64* q3 = (const u64*)qbuf[w][3];
        #pragma unroll
        for (int j = 0; j < 16; j++) {          // broadcast LDS.64, 4 indep chains
            a0 = fma2(q0[j], kv[j], a0);
            a1 = fma2(q1[j], kv[j], a1);
            a2 = fma2(q2[j], kv[j], a2);
            a3 = fma2(q3[j], kv[j], a3);
        }

        float t0 = qf[0] * ks, t1 = qf[1] * ks, t2 = qf[2] * ks, t3 = qf[3] * ks;
        #pragma unroll
        for (int m = 16; m >= 1; m >>= 1) {     // 4 interleaved butterflies
            t0 += __shfl_xor_sync(0xFFFFFFFFu, t0, m);
            t1 += __shfl_xor_sync(0xFFFFFFFFu, t1, m);
            t2 += __shfl_xor_sync(0xFFFFFFFFu, t2, m);
            t3 += __shfl_xor_sync(0xFFFFFFFFu, t3, m);
        }

        float2 u0 = unp(a0), u1 = unp(a1), u2 = unp(a2), u3 = unp(a3);
        out[base + (size_t)(r + 0) * RS] = (u0.x + u0.y) * __fdividef(1.f, t0 + 1e-6f);
        out[base + (size_t)(r + 1) * RS] = (u1.x + u1.y) * __fdividef(1.f, t1 + 1e-6f);
        out[base + (size_t)(r + 2) * RS] = (u2.x + u2.y) * __fdividef(1.f, t2 + 1e-6f);
        out[base + (size_t)(r + 3) * RS] = (u3.x + u3.y) * __fdividef(1.f, t3 + 1e-6f);
        __syncwarp();
    }
}

extern "C" void kernel_launch(void* const* d_in, const int* in_sizes, int n_in,
                              void* d_out, int out_size)
{
    const float* queries = (const float*)d_in[0];
    const float* keys    = (const float*)d_in[1];
    const float* values  = (const float*)d_in[2];
    float* out = (float*)d_out;

    phase1_kernel<<<dim3(NH, P1C), 256>>>(keys, values);
    phase2_kernel<<<dim3(NH, P2C), 256>>>(queries, out);
}

// round 5
// speedup vs baseline: 1.6945x; 1.2495x over previous
#include <cuda_runtime.h>
#include <cuda_bf16.h>

// Shape fixed for this dataset entry
#define NN 8
#define LL 8192
#define SS 8192
#define HH 8
#define RS 256              // floats per token row (H*D)
#define NH 64               // N*H

#define P1CH 64             // phase1 chunks per head
#define P1TOK 128           // tokens per warp-chunk
#define P1TILE 8            // tokens per pipeline stage
#define P1NT (P1TOK/P1TILE) // 16 stages
#define PART 1056           // 1024 KV (f32x2-pair layout) + 32 Ksum

// Deterministic scratch
__device__ __align__(16) float g_part[P1CH * NH * PART];   // ~17.3 MB
__device__ __align__(16) float g_red [NH * PART];          // reduced states

typedef unsigned long long u64;

__device__ __forceinline__ u64 fma2(u64 a, u64 b, u64 c) {
    u64 d;
    asm("fma.rn.f32x2 %0, %1, %2, %3;" : "=l"(d) : "l"(a), "l"(b), "l"(c));
    return d;
}
__device__ __forceinline__ u64 dup2(float v) {
    u64 d;
    asm("mov.b64 %0, {%1, %1};" : "=l"(d) : "f"(v));
    return d;
}
__device__ __forceinline__ float2 unp(u64 a) {
    float2 r;
    asm("mov.b64 {%0, %1}, %2;" : "=f"(r.x), "=f"(r.y) : "l"(a));
    return r;
}
__device__ __forceinline__ float elu1(float x) {
    return x > 0.0f ? x + 1.0f : __expf(x);   // elu(x)+1 = exp(x) for x<=0
}

// ---------------------------------------------------------------------------
// Phase 1: each WARP owns a full 32x32 KV accumulator (f32x2 pairs, lane = v
// column) for a private 128-token chunk. K staged through warp-private smem
// (syncwarp only), V kept in registers. Next 8 K + 8 V rows prefetched during
// compute. Epilogue: coalesced STG.64 of partial to g_part.
// Partial layout: p = j*64 + 2v + e  <->  KV[2j+e][v];  p=1024+d -> Ksum[d].
// ---------------------------------------------------------------------------
__global__ void __launch_bounds__(256)
phase1_kernel(const float* __restrict__ K, const float* __restrict__ V)
{
    __shared__ __align__(16) float sK[8][P1TILE * 32];   // per-warp stage

    const int tid = threadIdx.x;
    const int w = tid >> 5, lane = tid & 31;
    const int W = blockIdx.x * 8 + w;        // global warp id, 0..4095
    const int nh = W >> 6, chunk = W & (P1CH - 1);
    const int n = nh >> 3, h = nh & 7;

    const size_t tokbase = ((size_t)n * SS + (size_t)chunk * P1TOK) * RS + h * 32 + lane;
    const float* Kp = K + tokbase;
    const float* Vp = V + tokbase;
    float* sk = &sK[w][0];

    u64 acc[16];
    #pragma unroll
    for (int j = 0; j < 16; j++) acc[j] = 0ULL;
    float ksum = 0.f;

    float kr[P1TILE], vr[P1TILE];
    #pragma unroll
    for (int i = 0; i < P1TILE; i++) {       // prefetch stage 0
        kr[i] = Kp[(size_t)i * RS];
        vr[i] = Vp[(size_t)i * RS];
    }

    for (int t = 0; t < P1NT; ++t) {
        float vcur[P1TILE];
        #pragma unroll
        for (int i = 0; i < P1TILE; i++) {
            float e = elu1(kr[i]);
            ksum += e;
            sk[i * 32 + lane] = e;
            vcur[i] = vr[i];
        }
        __syncwarp();

        if (t + 1 < P1NT) {                  // prefetch next stage (front-batched)
            const float* Kn = Kp + (size_t)(t + 1) * P1TILE * RS;
            const float* Vn = Vp + (size_t)(t + 1) * P1TILE * RS;
            #pragma unroll
            for (int i = 0; i < P1TILE; i++) kr[i] = Kn[(size_t)i * RS];
            #pragma unroll
            for (int i = 0; i < P1TILE; i++) vr[i] = Vn[(size_t)i * RS];
        }

        #pragma unroll
        for (int i = 0; i < P1TILE; i++) {
            u64 v2 = dup2(vcur[i]);
            const u64* k2 = (const u64*)(sk + i * 32);   // broadcast LDS.64
            #pragma unroll
            for (int j = 0; j < 16; j++) acc[j] = fma2(k2[j], v2, acc[j]);
        }
        __syncwarp();
    }

    float* gp = g_part + ((size_t)chunk * NH + nh) * PART;
    #pragma unroll
    for (int j = 0; j < 16; j++)             // coalesced 256B STG.64 per j
        *(u64*)&gp[j * 64 + lane * 2] = acc[j];
    gp[1024 + lane] = ksum;
}

// ---------------------------------------------------------------------------
// Mid: reduce 64 chunk partials per head. One thread per (nh, f) element.
// ---------------------------------------------------------------------------
__global__ void __launch_bounds__(256)
reduce_kernel()
{
    const int g = blockIdx.x * 256 + threadIdx.x;   // 0 .. 64*1056-1
    if (g >= NH * PART) return;
    const int nh = g / PART, f = g - nh * PART;
    float s = 0.f;
    #pragma unroll 8
    for (int c = 0; c < P1CH; c++)
        s += g_part[((size_t)c * NH + nh) * PART + f];
    g_red[(size_t)nh * PART + f] = s;
}

// ---------------------------------------------------------------------------
// Phase 2: out = phi(Q) @ KV / (phi(Q).Ksum + eps).
// Lane holds KV column `lane` as 16 packed pairs (from g_red). 8 rows per
// pipeline stage: elu+stage to warp-private smem, prefetch next 8 Q rows,
// 8 independent FFMA2 chains, 8 interleaved shuffle butterflies for Z.
// No block-wide syncs.
// ---------------------------------------------------------------------------
__global__ void __launch_bounds__(256)
phase2_kernel(const float* __restrict__ Q, float* __restrict__ out)
{
    __shared__ __align__(16) float qbuf[8][8][32];

    const int tid = threadIdx.x;
    const int w = tid >> 5, lane = tid & 31;
    const int nh = blockIdx.x, chunk = blockIdx.y;   // 64 x 8
    const int n = nh >> 3, h = nh & 7;

    const float* red = g_red + (size_t)nh * PART;
    u64 kv[16];
    #pragma unroll
    for (int j = 0; j < 16; j++)
        kv[j] = __ldg((const u64*)&red[j * 64 + lane * 2]);
    const float ks = __ldg(&red[1024 + lane]);

    const size_t base = ((size_t)n * LL + (size_t)chunk * 1024 + w * 128) * RS + h * 32 + lane;
    const float* Qp = Q + base;
    float*       Op = out + base;

    float qr[8];
    #pragma unroll
    for (int i = 0; i < 8; i++) qr[i] = Qp[(size_t)i * RS];

    for (int g = 0; g < 16; ++g) {
        float qf[8];
        #pragma unroll
        for (int i = 0; i < 8; i++) {
            qf[i] = elu1(qr[i]);
            qbuf[w][i][lane] = qf[i];
        }
        __syncwarp();

        if (g + 1 < 16) {                    // prefetch next 8 rows
            const float* Qn = Qp + (size_t)(g + 1) * 8 * RS;
            #pragma unroll
            for (int i = 0; i < 8; i++) qr[i] = Qn[(size_t)i * RS];
        }

        u64 a[8];
        #pragma unroll
        for (int i = 0; i < 8; i++) a[i] = 0ULL;
        #pragma unroll
        for (int j = 0; j < 16; j++) {
            #pragma unroll
            for (int i = 0; i < 8; i++)      // broadcast LDS.64, 8 indep chains
                a[i] = fma2(*((const u64*)qbuf[w][i] + j), kv[j], a[i]);
        }

        float t[8];
        #pragma unroll
        for (int i = 0; i < 8; i++) t[i] = qf[i] * ks;
        #pragma unroll
        for (int m = 16; m >= 1; m >>= 1) {  // 8 interleaved butterflies
            #pragma unroll
            for (int i = 0; i < 8; i++)
                t[i] += __shfl_xor_sync(0xFFFFFFFFu, t[i], m);
        }

        #pragma unroll
        for (int i = 0; i < 8; i++) {
            float2 u = unp(a[i]);
            Op[(size_t)(g * 8 + i) * RS] = (u.x + u.y) * __fdividef(1.f, t[i] + 1e-6f);
        }
        __syncwarp();
    }
}

extern "C" void kernel_launch(void* const* d_in, const int* in_sizes, int n_in,
                              void* d_out, int out_size)
{
    const float* queries = (const float*)d_in[0];
    const float* keys    = (const float*)d_in[1];
    const float* values  = (const float*)d_in[2];
    float* out = (float*)d_out;

    phase1_kernel<<<NH * P1CH / 8, 256>>>(keys, values);
    reduce_kernel<<<(NH * PART + 255) / 256, 256>>>();
    phase2_kernel<<<dim3(NH, 8), 256>>>(queries, out);
}

// round 10
// speedup vs baseline: 1.8831x; 1.1113x over previous
#include <cuda_runtime.h>
#include <cuda_bf16.h>

// Shape fixed for this dataset entry
#define NN 8
#define LL 8192
#define SS 8192
#define HH 8
#define RS 256              // floats per token row (H*D)
#define NH 64               // N*H

#define P1CH 64             // phase1 chunks per head
#define P1TOK 128           // tokens per warp-chunk
#define P1TILE 4            // tokens per pipeline stage (regs!)
#define P1NT (P1TOK/P1TILE) // 32 stages
#define PART 1056           // 1024 KV (f32x2-pair layout) + 32 Ksum

#define P2C 16              // phase2 L-chunks (tail reduction)

// Deterministic scratch
__device__ __align__(16) float g_part[P1CH * NH * PART];   // ~17.3 MB
__device__ __align__(16) float g_red [NH * PART];          // reduced states

typedef unsigned long long u64;

__device__ __forceinline__ u64 fma2(u64 a, u64 b, u64 c) {
    u64 d;
    asm("fma.rn.f32x2 %0, %1, %2, %3;" : "=l"(d) : "l"(a), "l"(b), "l"(c));
    return d;
}
__device__ __forceinline__ u64 dup2(float v) {
    u64 d;
    asm("mov.b64 %0, {%1, %1};" : "=l"(d) : "f"(v));
    return d;
}
__device__ __forceinline__ float2 unp(u64 a) {
    float2 r;
    asm("mov.b64 {%0, %1}, %2;" : "=f"(r.x), "=f"(r.y) : "l"(a));
    return r;
}
__device__ __forceinline__ float elu1(float x) {
    return x > 0.0f ? x + 1.0f : __expf(x);   // elu(x)+1 = exp(x) for x<=0
}

// ---------------------------------------------------------------------------
// Phase 1: each WARP owns a full 32x32 KV accumulator (f32x2 pairs, lane = v
// column) over a private 128-token chunk. elu(K) staged in warp-private smem,
// broadcast back as LDS.128 (2 d-pairs per load). 4 K + 4 V rows prefetched
// per stage. __launch_bounds__(256,4) forces <=64 regs -> 4 CTA/SM (the
// occupancy condition of this experiment, enforced rather than hoped for).
// Partial layout: p = j*64 + 2v + e  <->  KV[2j+e][v];  p=1024+d -> Ksum[d].
// ---------------------------------------------------------------------------
__global__ void __launch_bounds__(256, 4)
phase1_kernel(const float* __restrict__ K, const float* __restrict__ V)
{
    __shared__ __align__(16) float sK[8][P1TILE * 32];   // per-warp stage

    const int tid = threadIdx.x;
    const int w = tid >> 5, lane = tid & 31;
    const int W = blockIdx.x * 8 + w;        // global warp id, 0..4095
    const int nh = W >> 6, chunk = W & (P1CH - 1);
    const int n = nh >> 3, h = nh & 7;

    const size_t tokbase = ((size_t)n * SS + (size_t)chunk * P1TOK) * RS + h * 32 + lane;
    const float* Kp = K + tokbase;
    const float* Vp = V + tokbase;
    float* sk = &sK[w][0];

    u64 acc[16];
    #pragma unroll
    for (int j = 0; j < 16; j++) acc[j] = 0ULL;
    float ksum = 0.f;

    float kr[P1TILE], vr[P1TILE];
    #pragma unroll
    for (int i = 0; i < P1TILE; i++) {       // prefetch stage 0
        kr[i] = Kp[(size_t)i * RS];
        vr[i] = Vp[(size_t)i * RS];
    }

    for (int t = 0; t < P1NT; ++t) {
        float vcur[P1TILE];
        #pragma unroll
        for (int i = 0; i < P1TILE; i++) {
            float e = elu1(kr[i]);
            ksum += e;
            sk[i * 32 + lane] = e;
            vcur[i] = vr[i];
        }
        __syncwarp();

        if (t + 1 < P1NT) {                  // prefetch next stage (front-batched)
            const float* Kn = Kp + (size_t)(t + 1) * P1TILE * RS;
            const float* Vn = Vp + (size_t)(t + 1) * P1TILE * RS;
            #pragma unroll
            for (int i = 0; i < P1TILE; i++) kr[i] = Kn[(size_t)i * RS];
            #pragma unroll
            for (int i = 0; i < P1TILE; i++) vr[i] = Vn[(size_t)i * RS];
        }

        #pragma unroll
        for (int i = 0; i < P1TILE; i++) {
            u64 v2 = dup2(vcur[i]);
            const ulonglong2* k2 = (const ulonglong2*)(sk + i * 32);  // LDS.128 bcast
            #pragma unroll
            for (int j = 0; j < 8; j++) {
                ulonglong2 kk = k2[j];
                acc[2 * j + 0] = fma2(kk.x, v2, acc[2 * j + 0]);
                acc[2 * j + 1] = fma2(kk.y, v2, acc[2 * j + 1]);
            }
        }
        __syncwarp();
    }

    float* gp = g_part + ((size_t)chunk * NH + nh) * PART;
    #pragma unroll
    for (int j = 0; j < 16; j++)             // coalesced 256B STG.64 per j
        *(u64*)&gp[j * 64 + lane * 2] = acc[j];
    gp[1024 + lane] = ksum;
}

// ---------------------------------------------------------------------------
// Mid: reduce 64 chunk partials per head. One thread per (nh, f) element.
// ---------------------------------------------------------------------------
__global__ void __launch_bounds__(256)
reduce_kernel()
{
    const int g = blockIdx.x * 256 + threadIdx.x;   // 0 .. 64*1056-1
    if (g >= NH * PART) return;
    const int nh = g / PART, f = g - nh * PART;
    float s = 0.f;
    #pragma unroll 8
    for (int c = 0; c < P1CH; c++)
        s += g_part[((size_t)c * NH + nh) * PART + f];
    g_red[(size_t)nh * PART + f] = s;
}

// ---------------------------------------------------------------------------
// Phase 2: out = phi(Q) @ KV / (phi(Q).Ksum + eps).
// Lane holds KV column `lane` as 16 packed pairs (from g_red). 8 rows per
// pipeline stage; q broadcast via LDS.128; Z-seed folded into elu step;
// 8 interleaved shuffle butterflies. Warp-private, no block syncs.
// ---------------------------------------------------------------------------
__global__ void __launch_bounds__(256)
phase2_kernel(const float* __restrict__ Q, float* __restrict__ out)
{
    __shared__ __align__(16) float qbuf[8][8][32];

    const int tid = threadIdx.x;
    const int w = tid >> 5, lane = tid & 31;
    const int nh = blockIdx.x, chunk = blockIdx.y;   // 64 x 16
    const int n = nh >> 3, h = nh & 7;

    const float* red = g_red + (size_t)nh * PART;
    u64 kv[16];
    #pragma unroll
    for (int j = 0; j < 16; j++)
        kv[j] = *(const u64*)&red[j * 64 + lane * 2];
    const float ks = red[1024 + lane];

    // 512 rows per block, 64 per warp, 8 stages of 8
    const size_t base = ((size_t)n * LL + (size_t)chunk * 512 + w * 64) * RS + h * 32 + lane;
    const float* Qp = Q + base;
    float*       Op = out + base;

    float qr[8];
    #pragma unroll
    for (int i = 0; i < 8; i++) qr[i] = Qp[(size_t)i * RS];

    for (int g = 0; g < 8; ++g) {
        float t[8];
        #pragma unroll
        for (int i = 0; i < 8; i++) {        // elu + stage + Z-seed (qf not kept)
            float qf = elu1(qr[i]);
            qbuf[w][i][lane] = qf;
            t[i] = qf * ks;
        }
        __syncwarp();

        if (g + 1 < 8) {                     // prefetch next 8 rows
            const float* Qn = Qp + (size_t)(g + 1) * 8 * RS;
            #pragma unroll
            for (int i = 0; i < 8; i++) qr[i] = Qn[(size_t)i * RS];
        }

        u64 a[8];
        #pragma unroll
        for (int i = 0; i < 8; i++) a[i] = 0ULL;
        #pragma unroll
        for (int j = 0; j < 8; j++) {
            #pragma unroll
            for (int i = 0; i < 8; i++) {    // LDS.128 bcast, 8 indep chains
                ulonglong2 qq = *((const ulonglong2*)qbuf[w][i] + j);
                a[i] = fma2(qq.x, kv[2 * j + 0], a[i]);
                a[i] = fma2(qq.y, kv[2 * j + 1], a[i]);
            }
        }

        #pragma unroll
        for (int m = 16; m >= 1; m >>= 1) {  // 8 interleaved butterflies
            #pragma unroll
            for (int i = 0; i < 8; i++)
                t[i] += __shfl_xor_sync(0xFFFFFFFFu, t[i], m);
        }

        #pragma unroll
        for (int i = 0; i < 8; i++) {
            float2 u = unp(a[i]);
            Op[(size_t)(g * 8 + i) * RS] = (u.x + u.y) * __fdividef(1.f, t[i] + 1e-6f);
        }
        __syncwarp();
    }
}

extern "C" void kernel_launch(void* const* d_in, const int* in_sizes, int n_in,
                              void* d_out, int out_size)
{
    const float* queries = (const float*)d_in[0];
    const float* keys    = (const float*)d_in[1];
    const float* values  = (const float*)d_in[2];
    float* out = (float*)d_out;

    phase1_kernel<<<NH * P1CH / 8, 256>>>(keys, values);
    reduce_kernel<<<(NH * PART + 255) / 256, 256>>>();
    phase2_kernel<<<dim3(NH, P2C), 256>>>(queries, out);
}